// round 15
// baseline (speedup 1.0000x reference)
#include <cuda_runtime.h>
#include <cstdint>
#include <math.h>

// Symmetric Hausdorff distance, B=4, N=M=8192, D=3, fp32.
// Morton-sorted windowed scan + threshold pruning. 3 launches.
//
// k_sort: 8 blocks (set x batch), smem counting sort by Morton cell
//         (16^3 over [-4,4]^3; clamping affects ordering only).
// k_seed: exact mins for 256 strided rows per (dir,batch) -> g_seedmin;
//         LAST finishing block reduces to per-batch threshold g_res[b]
//         (= max of exact row mins = valid lower bound of the answer).
// k_main: warp = 4 consecutive sorted rows sharing one 256-target window
//         centered at row0's Morton position in the opposite sorted array.
//         One prune check per row vs g_res[b] kills ~all rows; survivors do
//         a full pruned scan. Strict '<' prune + valid lower bound => the
//         argmax row always completes and publishes its exact min =>
//         exact, bitwise-deterministic output. LAST block writes out[].
//
// All min/max on int bit patterns of d^2 >= 0 (order == float order, exact).

#define BATCH 4
#define NPB 8192
#define TOT (2*BATCH*NPB)        // 65536
#define G 16
#define GC (G*G*G)               // 4096 cells per (set,batch)
#define RANGE 4.0f
#define INVH 2.0f
#define WIN 256
#define SEEDROWS 256
#define FINF_BITS 0x7f800000

__device__ float4 g_pts4[TOT];           // sorted points, [set][batch][slot]
__device__ int    g_cellstart[8*GC];
__device__ int    g_seedmin[8*SEEDROWS];
__device__ int    g_res[BATCH];
__device__ int    g_cnt_seed;            // zero-init; self-resetting tickets
__device__ int    g_cnt_main;

__device__ __forceinline__ int clampi(int v, int lo, int hi) {
    return v < lo ? lo : (v > hi ? hi : v);
}
__device__ __forceinline__ unsigned part1by2(unsigned x) {
    x = (x | (x << 16)) & 0x030000FFu;
    x = (x | (x << 8))  & 0x0300F00Fu;
    x = (x | (x << 4))  & 0x030C30C3u;
    x = (x | (x << 2))  & 0x09249249u;
    return x;
}
__device__ __forceinline__ int morton_cell(float x, float y, float z) {
    unsigned cx = (unsigned)clampi((int)floorf((x + RANGE) * INVH), 0, G - 1);
    unsigned cy = (unsigned)clampi((int)floorf((y + RANGE) * INVH), 0, G - 1);
    unsigned cz = (unsigned)clampi((int)floorf((z + RANGE) * INVH), 0, G - 1);
    return (int)(part1by2(cx) | (part1by2(cy) << 1) | (part1by2(cz) << 2));
}
__device__ __forceinline__ float dist2(const float4 q, const float4 t) {
    float dx = q.x - t.x, dy = q.y - t.y, dz = q.z - t.z;
    return fmaf(dx, dx, fmaf(dy, dy, dz * dz));
}

// One block per (set,batch): counting sort entirely in shared memory.
__global__ __launch_bounds__(1024) void k_sort(const float* __restrict__ pred,
                                               const float* __restrict__ gt) {
    __shared__ int hist[GC];
    __shared__ int scanb[GC];
    __shared__ int aux[1024];

    const int si  = blockIdx.x;                    // set*4 + batch
    const int tid = threadIdx.x;
    const float* __restrict__ src =
        (si < 4) ? (pred + (size_t)si * NPB * 3)
                 : (gt + (size_t)(si - 4) * NPB * 3);

    for (int c = tid; c < GC; c += 1024) hist[c] = 0;
    if (tid < SEEDROWS) g_seedmin[si * SEEDROWS + tid] = FINF_BITS;
    __syncthreads();

    float4 p[8]; int cid[8];
#pragma unroll
    for (int k = 0; k < 8; k++) {
        const int i = tid + k * 1024;
        const float* s = src + 3 * (size_t)i;
        p[k] = make_float4(s[0], s[1], s[2], 0.0f);
        cid[k] = morton_cell(p[k].x, p[k].y, p[k].z);
        atomicAdd(&hist[cid[k]], 1);
    }
    __syncthreads();

    const int base = tid * 4;
    int h0 = hist[base], h1 = hist[base+1], h2 = hist[base+2], h3 = hist[base+3];
    int ts = h0 + h1 + h2 + h3;
    aux[tid] = ts; __syncthreads();
    for (int o = 1; o < 1024; o <<= 1) {
        int a = (tid >= o) ? aux[tid - o] : 0;
        __syncthreads();
        aux[tid] += a;
        __syncthreads();
    }
    int off = aux[tid] - ts;
    scanb[base]     = off;
    scanb[base + 1] = off + h0;
    scanb[base + 2] = off + h0 + h1;
    scanb[base + 3] = off + h0 + h1 + h2;
    g_cellstart[si * GC + base]     = scanb[base];
    g_cellstart[si * GC + base + 1] = scanb[base + 1];
    g_cellstart[si * GC + base + 2] = scanb[base + 2];
    g_cellstart[si * GC + base + 3] = scanb[base + 3];
    hist[base] = 0; hist[base+1] = 0; hist[base+2] = 0; hist[base+3] = 0;
    __syncthreads();

#pragma unroll
    for (int k = 0; k < 8; k++) {
        int slot = scanb[cid[k]] + atomicAdd(&hist[cid[k]], 1);
        g_pts4[si * NPB + slot] = p[k];
    }
}

// 2048 warps: (db: 8) x (rowgroup: 64) x (target-slice: 4). Exact row mins.
// Last finishing block reduces g_seedmin -> g_res[b] (threshold).
__global__ __launch_bounds__(256) void k_seed() {
    __shared__ int s_ticket;
    __shared__ int red[256];
    const int warp = threadIdx.x >> 5, lane = threadIdx.x & 31;
    const int tid = threadIdx.x;
    const int gw = blockIdx.x * 8 + warp;
    const int ts = gw & 3, rg = (gw >> 2) & 63, db = gw >> 8;
    const int dir = db >> 2, b = db & 3;
    const float4* __restrict__ Q = g_pts4 + (size_t)dir * BATCH * NPB + (size_t)b * NPB;
    const float4* __restrict__ T = g_pts4 + (size_t)(1 - dir) * BATCH * NPB + (size_t)b * NPB;

    float4 q0 = Q[(rg*4+0)*32], q1 = Q[(rg*4+1)*32];
    float4 q2 = Q[(rg*4+2)*32], q3 = Q[(rg*4+3)*32];
    float r0 = __int_as_float(FINF_BITS), r1 = r0, r2 = r0, r3 = r0;
    const int j0 = ts * 2048;
#pragma unroll 2
    for (int j = j0 + lane; j < j0 + 2048; j += 32) {
        const float4 t = T[j];
        r0 = fminf(r0, dist2(q0, t));
        r1 = fminf(r1, dist2(q1, t));
        r2 = fminf(r2, dist2(q2, t));
        r3 = fminf(r3, dist2(q3, t));
    }
    unsigned m0 = __reduce_min_sync(0xffffffffu, (unsigned)__float_as_int(r0));
    unsigned m1 = __reduce_min_sync(0xffffffffu, (unsigned)__float_as_int(r1));
    unsigned m2 = __reduce_min_sync(0xffffffffu, (unsigned)__float_as_int(r2));
    unsigned m3 = __reduce_min_sync(0xffffffffu, (unsigned)__float_as_int(r3));
    if (lane == 0) {
        atomicMin(&g_seedmin[db*SEEDROWS + rg*4+0], (int)m0);
        atomicMin(&g_seedmin[db*SEEDROWS + rg*4+1], (int)m1);
        atomicMin(&g_seedmin[db*SEEDROWS + rg*4+2], (int)m2);
        atomicMin(&g_seedmin[db*SEEDROWS + rg*4+3], (int)m3);
    }

    // Last-block-done: compute thresholds.
    __threadfence();
    __syncthreads();
    if (tid == 0) s_ticket = atomicAdd(&g_cnt_seed, 1);
    __syncthreads();
    if (s_ticket == gridDim.x - 1) {
        for (int bb = 0; bb < BATCH; bb++) {
            int v = max(g_seedmin[bb*SEEDROWS + tid],
                        g_seedmin[(bb+4)*SEEDROWS + tid]);
            red[tid] = v; __syncthreads();
            for (int s = 128; s > 0; s >>= 1) {
                if (tid < s) red[tid] = max(red[tid], red[tid + s]);
                __syncthreads();
            }
            if (tid == 0) g_res[bb] = red[0];
            __syncthreads();
        }
        if (tid == 0) g_cnt_seed = 0;              // reset for next replay
    }
}

// Survivor: full pruned scan of one row. rmin carries the window partial.
__device__ __forceinline__ void full_row(const float4 q,
                                         const float4* __restrict__ T,
                                         int b, int lane, float rmin) {
    unsigned wm = FINF_BITS;
    for (int j0 = 0; j0 < NPB; j0 += 256) {
        int thr = __ldcg(&g_res[b]);               // stale only under-prunes
#pragma unroll
        for (int s = 0; s < 8; s++)
            rmin = fminf(rmin, dist2(q, T[j0 + s * 32 + lane]));
        wm = __reduce_min_sync(0xffffffffu, (unsigned)__float_as_int(rmin));
        if (__int_as_float((int)wm) < __int_as_float(thr)) return;
    }
    if (lane == 0) atomicMax(&g_res[b], (int)wm);  // exact completed row min
}

// 4096 blocks x 128 thr: warp = 4 consecutive sorted rows, shared window.
// Last finishing block writes out[] (after all atomicMax are visible).
__global__ __launch_bounds__(128) void k_main(float* __restrict__ out) {
    __shared__ int s_ticket;
    const int warp = threadIdx.x >> 5, lane = threadIdx.x & 31;
    const int gw = blockIdx.x * 4 + warp;          // 0..16383
    const int db = gw >> 11;                       // 0..7
    const int n0 = (gw & 2047) * 4;                // 0..8188
    const int dir = db >> 2, b = db & 3;
    const float4* __restrict__ Q = g_pts4 + (size_t)dir * BATCH * NPB + (size_t)b * NPB;
    const float4* __restrict__ T = g_pts4 + (size_t)(1 - dir) * BATCH * NPB + (size_t)b * NPB;

    const float4 q0 = Q[n0], q1 = Q[n0+1], q2 = Q[n0+2], q3 = Q[n0+3];
    // Shared window centered at row1's cell position in the opposite array.
    int pos = g_cellstart[((1 - dir) * 4 + b) * GC + morton_cell(q1.x, q1.y, q1.z)];
    int start = clampi(pos - WIN / 2, 0, NPB - WIN);

    float r0 = __int_as_float(FINF_BITS), r1 = r0, r2 = r0, r3 = r0;
#pragma unroll
    for (int s = 0; s < WIN / 32; s++) {           // 8 coalesced LDG.128 steps
        const float4 t = T[start + s * 32 + lane]; // 1 load -> 4 rows
        r0 = fminf(r0, dist2(q0, t));
        r1 = fminf(r1, dist2(q1, t));
        r2 = fminf(r2, dist2(q2, t));
        r3 = fminf(r3, dist2(q3, t));
    }
    unsigned m0 = __reduce_min_sync(0xffffffffu, (unsigned)__float_as_int(r0));
    unsigned m1 = __reduce_min_sync(0xffffffffu, (unsigned)__float_as_int(r1));
    unsigned m2 = __reduce_min_sync(0xffffffffu, (unsigned)__float_as_int(r2));
    unsigned m3 = __reduce_min_sync(0xffffffffu, (unsigned)__float_as_int(r3));
    const int thr = __ldcg(&g_res[b]);             // valid lower bound
    const float ft = __int_as_float(thr);
    // ~all rows prune here; rare survivors do full exact (pruned) scans.
    if (__int_as_float((int)m0) >= ft) full_row(q0, T, b, lane, r0);
    if (__int_as_float((int)m1) >= ft) full_row(q1, T, b, lane, r1);
    if (__int_as_float((int)m2) >= ft) full_row(q2, T, b, lane, r2);
    if (__int_as_float((int)m3) >= ft) full_row(q3, T, b, lane, r3);

    // Last-block-done: publish outputs.
    __threadfence();
    __syncthreads();
    if (threadIdx.x == 0) s_ticket = atomicAdd(&g_cnt_main, 1);
    __syncthreads();
    if (s_ticket == gridDim.x - 1) {
        if (threadIdx.x < BATCH)
            out[threadIdx.x] = sqrtf(__int_as_float(g_res[threadIdx.x]));
        if (threadIdx.x == 0) g_cnt_main = 0;      // reset for next replay
    }
}

extern "C" void kernel_launch(void* const* d_in, const int* in_sizes, int n_in,
                              void* d_out, int out_size) {
    const float* pred = (const float*)d_in[0];
    const float* gt   = (const float*)d_in[1];
    float* out = (float*)d_out;

    k_sort<<<8, 1024>>>(pred, gt);
    k_seed<<<256, 256>>>();
    k_main<<<4096, 128>>>(out);
}

// round 17
// speedup vs baseline: 1.2268x; 1.2268x over previous
#include <cuda_runtime.h>
#include <cstdint>
#include <math.h>

// Symmetric Hausdorff distance, B=4, N=M=8192, D=3, fp32.
// ONE persistent kernel (512 blocks x 128 thr, <=4 blocks/SM -> co-resident,
// grid spin-barriers are safe). Phases: prep -> seed -> thresh -> pruned main.
//
// s(n,m) = 0.5|x|^2 + 0.5|y|^2 - x.y = 0.5 d^2. Query form {x, 0.5|x|^2},
// target form {-y, 0.5|y|^2}: s = fma(qx,tx, fma(qy,ty, fma(qz,tz, qw+tw))).
//
// Pruning: a row cannot be the Hausdorff argmax once ANY lane's partial min
// over scanned targets is < thr, where thr (g_res[b]) is the running max of
// COMPLETED rows' exact mins (a valid lower bound of the answer; one
// threshold serves both directions since out = max of the two). Strict '<'
// => the argmax row always completes and publishes its exact min => output
// exact and bitwise deterministic regardless of work-stealing order.
// All min/max on int bit patterns of clamped d^2 >= 0 (order == float order).

#define BATCH 4
#define NPB 8192
#define SETPTS (BATCH*NPB)       // 32768
#define TOT (2*SETPTS)           // 65536
#define NBLK 512
#define NTHR 128
#define SEEDROWS 256
#define FINF_BITS 0x7f800000

__device__ float4 g_q4[TOT];             // {x, y, z, 0.5|p|^2}
__device__ float4 g_t4[TOT];             // {-x, -y, -z, 0.5|p|^2}
__device__ int    g_seedmin[8*SEEDROWS];
__device__ int    g_res[BATCH];
__device__ int    g_rowctr;              // work-steal ticket (reset at end)
__device__ int    g_bar_cnt;             // barrier arrivals (self-resetting)
__device__ volatile int g_bar_gen;       // barrier generation (monotonic)

__device__ __forceinline__ void gridbar() {
    __syncthreads();
    if (threadIdx.x == 0) {
        __threadfence();                          // publish this block's data
        int gen = g_bar_gen;
        if (atomicAdd(&g_bar_cnt, 1) == NBLK - 1) {
            g_bar_cnt = 0;
            __threadfence();
            g_bar_gen = gen + 1;
        } else {
            while (g_bar_gen == gen) __nanosleep(64);
        }
    }
    __syncthreads();
}

__device__ __forceinline__ float sfun(const float4 q, const float4 t) {
    return fmaf(q.x, t.x, fmaf(q.y, t.y, fmaf(q.z, t.z, q.w + t.w)));
}

__global__ __launch_bounds__(NTHR, 4) void hd_all(const float* __restrict__ pred,
                                                  const float* __restrict__ gt,
                                                  float* __restrict__ out) {
    const int tid  = threadIdx.x;
    const int warp = tid >> 5, lane = tid & 31;
    const int gtid = blockIdx.x * NTHR + tid;     // 0..65535

    // ---- Phase 0: prep (1 point/thread) ----
    {
        const float* s = (gtid < SETPTS) ? (pred + 3 * (size_t)gtid)
                                         : (gt + 3 * (size_t)(gtid - SETPTS));
        float x = s[0], y = s[1], z = s[2];
        float c = 0.5f * (x*x + y*y + z*z);
        g_q4[gtid] = make_float4(x, y, z, c);
        g_t4[gtid] = make_float4(-x, -y, -z, c);
        if (gtid < 8 * SEEDROWS) g_seedmin[gtid] = FINF_BITS;
    }
    gridbar();

    // ---- Phase 1: seed (2048 warps: 8 db x 64 rowgroups x 4 target slices) ----
    {
        const int gw = blockIdx.x * 4 + warp;     // 0..2047
        const int ts = gw & 3, rg = (gw >> 2) & 63, db = gw >> 8;
        const int dir = db >> 2, b = db & 3;
        const float4* __restrict__ Q = g_q4 + (size_t)dir * SETPTS + (size_t)b * NPB;
        const float4* __restrict__ T = g_t4 + (size_t)(1 - dir) * SETPTS + (size_t)b * NPB;

        float4 q0 = Q[(rg*4+0)*32], q1 = Q[(rg*4+1)*32];
        float4 q2 = Q[(rg*4+2)*32], q3 = Q[(rg*4+3)*32];
        float r0 = __int_as_float(FINF_BITS), r1 = r0, r2 = r0, r3 = r0;
        const int j0 = ts * 2048;
#pragma unroll 2
        for (int j = j0 + lane; j < j0 + 2048; j += 32) {
            const float4 t = T[j];                // one LDG.128 feeds 4 rows
            r0 = fminf(r0, sfun(q0, t));
            r1 = fminf(r1, sfun(q1, t));
            r2 = fminf(r2, sfun(q2, t));
            r3 = fminf(r3, sfun(q3, t));
        }
        // Publish as clamped d^2 bits (monotone: min then clamp+double).
        unsigned m0 = __reduce_min_sync(0xffffffffu,
                        (unsigned)__float_as_int(fmaxf(2.0f*r0, 0.0f)));
        unsigned m1 = __reduce_min_sync(0xffffffffu,
                        (unsigned)__float_as_int(fmaxf(2.0f*r1, 0.0f)));
        unsigned m2 = __reduce_min_sync(0xffffffffu,
                        (unsigned)__float_as_int(fmaxf(2.0f*r2, 0.0f)));
        unsigned m3 = __reduce_min_sync(0xffffffffu,
                        (unsigned)__float_as_int(fmaxf(2.0f*r3, 0.0f)));
        if (lane == 0) {
            atomicMin(&g_seedmin[db*SEEDROWS + rg*4+0], (int)m0);
            atomicMin(&g_seedmin[db*SEEDROWS + rg*4+1], (int)m1);
            atomicMin(&g_seedmin[db*SEEDROWS + rg*4+2], (int)m2);
            atomicMin(&g_seedmin[db*SEEDROWS + rg*4+3], (int)m3);
        }
    }
    gridbar();

    // ---- Phase 2: thresholds (block 0 only) ----
    if (blockIdx.x == 0) {
        __shared__ int red[NTHR];
        for (int bb = 0; bb < BATCH; bb++) {
            int v = max(max(g_seedmin[bb*SEEDROWS + tid],
                            g_seedmin[bb*SEEDROWS + tid + 128]),
                        max(g_seedmin[(bb+4)*SEEDROWS + tid],
                            g_seedmin[(bb+4)*SEEDROWS + tid + 128]));
            red[tid] = v; __syncthreads();
            for (int s = 64; s > 0; s >>= 1) {
                if (tid < s) red[tid] = max(red[tid], red[tid + s]);
                __syncthreads();
            }
            if (tid == 0) g_res[bb] = red[0];
            __syncthreads();
        }
    }
    gridbar();

    // ---- Phase 3: main — pruned scans with warp work-stealing ----
    {
        for (;;) {
            int r0w = 0;
            if (lane == 0) r0w = atomicAdd(&g_rowctr, 8);
            r0w = __shfl_sync(0xffffffffu, r0w, 0);
            if (r0w >= TOT) break;
            const int rend = min(r0w + 8, TOT);
            for (int r = r0w; r < rend; r++) {
                const int db = r >> 13, n = r & (NPB - 1);
                const int dir = db >> 2, b = db & 3;
                const float4* __restrict__ Q = g_q4 + (size_t)dir * SETPTS + (size_t)b * NPB;
                const float4* __restrict__ T = g_t4 + (size_t)(1 - dir) * SETPTS + (size_t)b * NPB;
                const float4 q = Q[n];
                float rm = __int_as_float(FINF_BITS);  // per-lane partial (s units)
                bool pruned = false;
                for (int j0 = 0; j0 < NPB && !pruned; j0 += 1024) {
                    // refresh threshold (stale read only under-prunes); s units
                    const float ft = 0.5f * __int_as_float(__ldcg(&g_res[b]));
#pragma unroll
                    for (int c = 0; c < 8; c++) {      // 8 chunks of 128 targets
                        const int jb = j0 + c * 128 + lane;
#pragma unroll
                        for (int s = 0; s < 4; s++)
                            rm = fminf(rm, sfun(q, T[jb + s * 32]));
                        // lane partial < thr already proves row min < thr
                        if (__any_sync(0xffffffffu, rm < ft)) { pruned = true; break; }
                    }
                }
                if (!pruned) {
                    unsigned wm = __reduce_min_sync(0xffffffffu,
                                    (unsigned)__float_as_int(fmaxf(2.0f*rm, 0.0f)));
                    if (lane == 0) atomicMax(&g_res[b], (int)wm);  // exact row min
                }
            }
        }
    }
    gridbar();

    // ---- Phase 4: publish + reset tickets (block 0) ----
    if (blockIdx.x == 0) {
        if (tid < BATCH) out[tid] = sqrtf(__int_as_float(g_res[tid]));
        if (tid == 0) g_rowctr = 0;                  // next graph replay
    }
}

extern "C" void kernel_launch(void* const* d_in, const int* in_sizes, int n_in,
                              void* d_out, int out_size) {
    const float* pred = (const float*)d_in[0];
    const float* gt   = (const float*)d_in[1];
    float* out = (float*)d_out;

    hd_all<<<NBLK, NTHR>>>(pred, gt, out);
}